// round 4
// baseline (speedup 1.0000x reference)
#include <cuda_runtime.h>
#include <cuda_bf16.h>
#include <cstdint>

#define NB 1024
#define NV 64
#define NI 256
#define NO 256
constexpr float EPS = 1e-5f;

// ---------------------------------------------------------------------------
// Device scratch
// ---------------------------------------------------------------------------
__device__ float g_h[(size_t)NB * NV * NO];            // 64 MB: h = feat@W + b
__device__ __nv_bfloat16 g_Whi[(size_t)NV * NO * NI];  // 8 MB, layout [v][o][i]
__device__ __nv_bfloat16 g_Wlo[(size_t)NV * NO * NI];  // 8 MB
__device__ __nv_bfloat16 g_adjhi[NV * NV];
__device__ __nv_bfloat16 g_adjlo[NV * NV];
__device__ float g_s[NV * NO];
__device__ float g_t[NV * NO];

// ---------------------------------------------------------------------------
// Helpers (baseline PTX only)
// ---------------------------------------------------------------------------
__device__ __forceinline__ uint32_t smem_u32(const void* p) {
    uint32_t a;
    asm("{ .reg .u64 t; cvta.to.shared.u64 t, %1; cvt.u32.u64 %0, t; }"
        : "=r"(a) : "l"(p));
    return a;
}
#define SWZ(off) ((uint32_t)(off) ^ ((((uint32_t)(off)) >> 3) & 0x70))

__device__ __forceinline__ void ldsm_x4(uint32_t* r, uint32_t addr) {
    asm volatile("ldmatrix.sync.aligned.m8n8.x4.shared.b16 {%0,%1,%2,%3}, [%4];"
                 : "=r"(r[0]), "=r"(r[1]), "=r"(r[2]), "=r"(r[3]) : "r"(addr));
}
__device__ __forceinline__ void ldsm_x2(uint32_t* r, uint32_t addr) {
    asm volatile("ldmatrix.sync.aligned.m8n8.x2.shared.b16 {%0,%1}, [%2];"
                 : "=r"(r[0]), "=r"(r[1]) : "r"(addr));
}
__device__ __forceinline__ void ldsm_x2t(uint32_t* r, uint32_t addr) {
    asm volatile("ldmatrix.sync.aligned.m8n8.x2.trans.shared.b16 {%0,%1}, [%2];"
                 : "=r"(r[0]), "=r"(r[1]) : "r"(addr));
}
__device__ __forceinline__ void mma_bf16(float* d, const uint32_t* a,
                                         const uint32_t* b) {
    asm volatile(
        "mma.sync.aligned.m16n8k16.row.col.f32.bf16.bf16.f32 "
        "{%0,%1,%2,%3}, {%4,%5,%6,%7}, {%8,%9}, {%0,%1,%2,%3};"
        : "+f"(d[0]), "+f"(d[1]), "+f"(d[2]), "+f"(d[3])
        : "r"(a[0]), "r"(a[1]), "r"(a[2]), "r"(a[3]), "r"(b[0]), "r"(b[1]));
}

// ---------------------------------------------------------------------------
// Kernel A: split W into bf16 hi/lo, transposed to K-major [v][o][i]
// ---------------------------------------------------------------------------
__global__ __launch_bounds__(256) void convert_W(const float* __restrict__ W) {
    __shared__ float tile[256][65];
    const int v = blockIdx.y, o0 = blockIdx.x * 64;
    const int t = threadIdx.x;
    const float* src = W + (size_t)v * NI * NO + o0;
#pragma unroll 8
    for (int r = 0; r < 64; r++) {
        int idx = r * 256 + t;
        int i = idx >> 6, o = idx & 63;
        tile[i][o] = src[(size_t)i * NO + o];
    }
    __syncthreads();
    __nv_bfloat16* dh = g_Whi + ((size_t)v * NO + o0) * NI;
    __nv_bfloat16* dl = g_Wlo + ((size_t)v * NO + o0) * NI;
#pragma unroll 8
    for (int r = 0; r < 64; r++) {
        float x = tile[t][r];
        __nv_bfloat16 hi = __float2bfloat16(x);
        __nv_bfloat16 lo = __float2bfloat16(x - __bfloat162float(hi));
        dh[(size_t)r * NI + t] = hi;
        dl[(size_t)r * NI + t] = lo;
    }
}

// ---------------------------------------------------------------------------
// Kernel A2: split adj into bf16 hi/lo. grid 16 x 256.
// ---------------------------------------------------------------------------
__global__ void convert_adj(const float* __restrict__ adj) {
    int i = blockIdx.x * 256 + threadIdx.x;   // 4096
    float x = adj[i];
    __nv_bfloat16 hi = __float2bfloat16(x);
    g_adjhi[i] = hi;
    g_adjlo[i] = __float2bfloat16(x - __bfloat162float(hi));
}

// ---------------------------------------------------------------------------
// Kernel B: mma.sync split-bf16 GEMM  h[m,v,:] = feat[m,v,:] @ W[v] + bias[v]
// ---------------------------------------------------------------------------
static constexpr int A_HI = 0;
static constexpr int A_LO = 16384;
static constexpr int B_HI = 32768;
static constexpr int B_LO = 49152;
static constexpr int GEMM_DSMEM = 65536 + 1024;

__global__ __launch_bounds__(256, 2) void gemm_mma(const float* __restrict__ feat,
                                                   const float* __restrict__ bias) {
    extern __shared__ char dynraw[];
    uint32_t rawa = smem_u32(dynraw);
    char* smb = dynraw + (((rawa + 1023) & ~1023u) - rawa);
    const uint32_t aHi = smem_u32(smb);

    const int v  = blockIdx.z;
    const int m0 = blockIdx.x * 128;
    const int n0 = blockIdx.y * 128;
    const int t  = threadIdx.x;
    const int lane = t & 31;
    const int w = t >> 5;
    const int mw = (w >> 2) * 64;
    const int nw = (w & 3) * 32;

    float acc[4][4][4];
#pragma unroll
    for (int i = 0; i < 4; i++)
#pragma unroll
        for (int j = 0; j < 4; j++)
#pragma unroll
            for (int q = 0; q < 4; q++) acc[i][j][q] = 0.f;

    const __nv_bfloat16* Wh = g_Whi + ((size_t)v * NO + n0) * NI;
    const __nv_bfloat16* Wl = g_Wlo + ((size_t)v * NO + n0) * NI;

    for (int c = 0; c < 4; c++) {
        const int k0 = c * 64;
        if (c) __syncthreads();

#pragma unroll
        for (int r = 0; r < 8; r++) {
            int idx = t + r * 256;
            int m = idx >> 4, kq = idx & 15;
            float4 x = *(const float4*)(feat +
                        ((size_t)(m0 + m) * NV + v) * NI + k0 + kq * 4);
            __nv_bfloat16 h0 = __float2bfloat16(x.x);
            __nv_bfloat16 h1 = __float2bfloat16(x.y);
            __nv_bfloat16 h2 = __float2bfloat16(x.z);
            __nv_bfloat16 h3 = __float2bfloat16(x.w);
            __nv_bfloat16 l0 = __float2bfloat16(x.x - __bfloat162float(h0));
            __nv_bfloat16 l1 = __float2bfloat16(x.y - __bfloat162float(h1));
            __nv_bfloat16 l2 = __float2bfloat16(x.z - __bfloat162float(h2));
            __nv_bfloat16 l3 = __float2bfloat16(x.w - __bfloat162float(h3));
            uint32_t off = SWZ(m * 128 + kq * 8);
            __nv_bfloat162 hp0 = {h0, h1}, hp1 = {h2, h3};
            __nv_bfloat162 lp0 = {l0, l1}, lp1 = {l2, l3};
            *(uint2*)(smb + A_HI + off) =
                make_uint2(*(uint32_t*)&hp0, *(uint32_t*)&hp1);
            *(uint2*)(smb + A_LO + off) =
                make_uint2(*(uint32_t*)&lp0, *(uint32_t*)&lp1);
        }
#pragma unroll
        for (int r = 0; r < 4; r++) {
            int idx = t + r * 256;
            int n = idx >> 3, kc = idx & 7;
            uint32_t off = SWZ(n * 128 + kc * 16);
            *(uint4*)(smb + B_HI + off) =
                *(const uint4*)(Wh + (size_t)n * NI + k0 + kc * 8);
            *(uint4*)(smb + B_LO + off) =
                *(const uint4*)(Wl + (size_t)n * NI + k0 + kc * 8);
        }
        __syncthreads();

#pragma unroll
        for (int ks = 0; ks < 4; ks++) {
            uint32_t bh[4][2], bl[4][2];
            {
                int brow = nw + (lane & 7);
                int bk = ks * 16 + ((lane >> 3) & 1) * 8;
#pragma unroll
                for (int nt = 0; nt < 4; nt++) {
                    uint32_t addr =
                        aHi + B_HI + SWZ((brow + nt * 8) * 128 + bk * 2);
                    ldsm_x2(bh[nt], addr);
                    ldsm_x2(bl[nt], addr + (B_LO - B_HI));
                }
            }
            int arow = mw + (lane & 7) + ((lane >> 3) & 1) * 8;
            int ak = ks * 16 + ((lane >> 4) & 1) * 8;
#pragma unroll
            for (int mt = 0; mt < 4; mt++) {
                uint32_t ra[4], rl[4];
                uint32_t addr = aHi + SWZ((arow + mt * 16) * 128 + ak * 2);
                ldsm_x4(ra, addr);
                ldsm_x4(rl, addr + A_LO);
#pragma unroll
                for (int nt = 0; nt < 4; nt++) {
                    mma_bf16(acc[mt][nt], ra, bh[nt]);
                    mma_bf16(acc[mt][nt], ra, bl[nt]);
                    mma_bf16(acc[mt][nt], rl, bh[nt]);
                }
            }
        }
    }

#pragma unroll
    for (int mt = 0; mt < 4; mt++) {
        int mlo = m0 + mw + mt * 16 + (lane >> 2);
#pragma unroll
        for (int nt = 0; nt < 4; nt++) {
            int n = n0 + nw + nt * 8 + (lane & 3) * 2;
            float2 bv = *(const float2*)(bias + v * NO + n);
            float2 o0, o1;
            o0.x = acc[mt][nt][0] + bv.x;
            o0.y = acc[mt][nt][1] + bv.y;
            o1.x = acc[mt][nt][2] + bv.x;
            o1.y = acc[mt][nt][3] + bv.y;
            *(float2*)(g_h + (size_t)mlo * (NV * NO) + v * NO + n) = o0;
            *(float2*)(g_h + (size_t)(mlo + 8) * (NV * NO) + v * NO + n) = o1;
        }
    }
}

// ---------------------------------------------------------------------------
// Kernel C: BN stats + fold, float4 per thread. grid 16 x 256.
// ---------------------------------------------------------------------------
__global__ __launch_bounds__(256) void stats_st(const float* __restrict__ gamma,
                                                const float* __restrict__ beta) {
    const int c4 = blockIdx.x * 256 + threadIdx.x;   // 0..4095 (col = c4*4)
    const float4* p = (const float4*)g_h + c4;
    float4 sum = make_float4(0.f, 0.f, 0.f, 0.f);
    float4 sq  = make_float4(0.f, 0.f, 0.f, 0.f);
#pragma unroll 8
    for (int b = 0; b < NB; b++) {
        float4 x = p[(size_t)b * 4096];
        sum.x += x.x; sum.y += x.y; sum.z += x.z; sum.w += x.w;
        sq.x = fmaf(x.x, x.x, sq.x); sq.y = fmaf(x.y, x.y, sq.y);
        sq.z = fmaf(x.z, x.z, sq.z); sq.w = fmaf(x.w, x.w, sq.w);
    }
    float4 gm = ((const float4*)gamma)[c4];
    float4 bt = ((const float4*)beta)[c4];
    float4 sv, tv;
#define DO_COMP(c)                                                  \
    {                                                               \
        float mean = sum.c * (1.f / NB);                            \
        float var  = sq.c * (1.f / NB) - mean * mean;               \
        float s    = gm.c * rsqrtf(var + EPS);                      \
        sv.c = s;                                                   \
        tv.c = fmaf(-mean, s, bt.c);                                \
    }
    DO_COMP(x) DO_COMP(y) DO_COMP(z) DO_COMP(w)
#undef DO_COMP
    ((float4*)g_s)[c4] = sv;
    ((float4*)g_t)[c4] = tv;
}

// ---------------------------------------------------------------------------
// Kernel D: tensorized mix.
// out[b,u,o] = relu( sum_v adj[u,v] * (s[v,o]*h[b,v,o] + t[v,o]) )
// D[u][o] = A[u][v] (adj, row-major) x B[o][v] (hs^T via ldmatrix.trans)
// one block per b, 8 warps: warp tile m16 x n128, K=64, 3 bf16 terms.
// ---------------------------------------------------------------------------
static constexpr int OPAD = 264;                 // hs row stride (bf16 elems)
static constexpr int HS_HI = 0;                  // 64*264*2 = 33792 B
static constexpr int HS_LO = 33792;
static constexpr int ADJ_HI = 67584;             // 64 rows x 72 elems x 2B
static constexpr int ADJ_LO = 76800;
static constexpr int MIX_DSMEM = 86016 + 1024;

__global__ __launch_bounds__(256, 2) void mix_tc(float* __restrict__ out) {
    extern __shared__ char dynraw[];
    uint32_t rawa = smem_u32(dynraw);
    char* smb = dynraw + (((rawa + 1023) & ~1023u) - rawa);
    const uint32_t sbase = smem_u32(smb);

    const int b = blockIdx.x;
    const int t = threadIdx.x;
    const int lane = t & 31;
    const int w = t >> 5;

    // ---- stage hs = s*h + t, split bf16 hi/lo, [v][OPAD] layout
    const float4* h4 = (const float4*)(g_h + (size_t)b * NV * NO);
    const float4* s4 = (const float4*)g_s;
    const float4* t4 = (const float4*)g_t;
#pragma unroll
    for (int r = 0; r < 16; r++) {
        int idx = t + r * 256;            // 0..4095
        int v = idx >> 6, oq = idx & 63;  // o = oq*4
        float4 h = h4[idx], sv = s4[idx], tv = t4[idx];
        float x0 = fmaf(h.x, sv.x, tv.x);
        float x1 = fmaf(h.y, sv.y, tv.y);
        float x2 = fmaf(h.z, sv.z, tv.z);
        float x3 = fmaf(h.w, sv.w, tv.w);
        __nv_bfloat16 h0 = __float2bfloat16(x0);
        __nv_bfloat16 h1 = __float2bfloat16(x1);
        __nv_bfloat16 h2 = __float2bfloat16(x2);
        __nv_bfloat16 h3 = __float2bfloat16(x3);
        __nv_bfloat16 l0 = __float2bfloat16(x0 - __bfloat162float(h0));
        __nv_bfloat16 l1 = __float2bfloat16(x1 - __bfloat162float(h1));
        __nv_bfloat16 l2 = __float2bfloat16(x2 - __bfloat162float(h2));
        __nv_bfloat16 l3 = __float2bfloat16(x3 - __bfloat162float(h3));
        __nv_bfloat162 hp0 = {h0, h1}, hp1 = {h2, h3};
        __nv_bfloat162 lp0 = {l0, l1}, lp1 = {l2, l3};
        uint32_t off = (uint32_t)(v * (OPAD * 2) + oq * 8);
        *(uint2*)(smb + HS_HI + off) =
            make_uint2(*(uint32_t*)&hp0, *(uint32_t*)&hp1);
        *(uint2*)(smb + HS_LO + off) =
            make_uint2(*(uint32_t*)&lp0, *(uint32_t*)&lp1);
    }
    // ---- stage adj hi/lo, [u][72] layout (pad for conflict-free ldmatrix)
#pragma unroll
    for (int r = 0; r < 8; r++) {
        int idx = t + r * 256;            // 0..2047 uint32s (2 bf16 each)
        int u = idx >> 5, q = idx & 31;
        *(uint32_t*)(smb + ADJ_HI + u * 144 + q * 4) =
            ((const uint32_t*)g_adjhi)[idx];
        *(uint32_t*)(smb + ADJ_LO + u * 144 + q * 4) =
            ((const uint32_t*)g_adjlo)[idx];
    }
    __syncthreads();

    const int mw = (w >> 1) * 16;     // u tile (4 tiles of 16)
    const int nw = (w & 1) * 128;     // o half

    float acc[16][4];
#pragma unroll
    for (int i = 0; i < 16; i++)
#pragma unroll
        for (int q = 0; q < 4; q++) acc[i][q] = 0.f;

#pragma unroll
    for (int ks = 0; ks < 4; ks++) {
        uint32_t ah[4], al[4];
        uint32_t aaddr = sbase + ADJ_HI + (mw + (lane & 15)) * 144 +
                         (ks * 16 + (lane >> 4) * 8) * 2;
        ldsm_x4(ah, aaddr);
        ldsm_x4(al, aaddr + (ADJ_LO - ADJ_HI));

        uint32_t brow = sbase + HS_HI + (ks * 16 + (lane & 15)) * (OPAD * 2);
#pragma unroll
        for (int nt = 0; nt < 16; nt++) {
            int n0 = nw + nt * 8;
            uint32_t bh[2], bl[2];
            ldsm_x2t(bh, brow + n0 * 2);
            ldsm_x2t(bl, brow + n0 * 2 + (HS_LO - HS_HI));
            mma_bf16(acc[nt], ah, bh);   // hi*hi
            mma_bf16(acc[nt], ah, bl);   // hi*lo
            mma_bf16(acc[nt], al, bh);   // lo*hi
        }
    }

    // ---- epilogue: relu + store
    float* ob = out + (size_t)b * NV * NO;
    const int u0 = mw + (lane >> 2);
#pragma unroll
    for (int nt = 0; nt < 16; nt++) {
        int o = nw + nt * 8 + (lane & 3) * 2;
        float2 r0, r1;
        r0.x = fmaxf(acc[nt][0], 0.f);
        r0.y = fmaxf(acc[nt][1], 0.f);
        r1.x = fmaxf(acc[nt][2], 0.f);
        r1.y = fmaxf(acc[nt][3], 0.f);
        *(float2*)(ob + (size_t)u0 * NO + o) = r0;
        *(float2*)(ob + (size_t)(u0 + 8) * NO + o) = r1;
    }
}

// ---------------------------------------------------------------------------
extern "C" void kernel_launch(void* const* d_in, const int* in_sizes, int n_in,
                              void* d_out, int out_size) {
    const float* feat  = (const float*)d_in[0];
    const float* adj   = (const float*)d_in[1];
    const float* W     = (const float*)d_in[2];
    const float* bias  = (const float*)d_in[3];
    const float* gamma = (const float*)d_in[4];
    const float* beta  = (const float*)d_in[5];
    float* out = (float*)d_out;

    cudaFuncSetAttribute(gemm_mma, cudaFuncAttributeMaxDynamicSharedMemorySize,
                         GEMM_DSMEM);
    cudaFuncSetAttribute(mix_tc, cudaFuncAttributeMaxDynamicSharedMemorySize,
                         MIX_DSMEM);

    convert_W<<<dim3(NO / 64, NV), 256>>>(W);
    convert_adj<<<16, 256>>>(adj);
    gemm_mma<<<dim3(NB / 128, NO / 128, NV), 256, GEMM_DSMEM>>>(feat, bias);
    stats_st<<<16, 256>>>(gamma, beta);
    mix_tc<<<NB, 256, MIX_DSMEM>>>(out);
}

// round 5
// speedup vs baseline: 1.0057x; 1.0057x over previous
#include <cuda_runtime.h>
#include <cuda_bf16.h>
#include <cstdint>

#define NB 1024
#define NV 64
#define NI 256
#define NO 256
constexpr float EPS = 1e-5f;

// ---------------------------------------------------------------------------
// Device scratch
// ---------------------------------------------------------------------------
__device__ float g_h[(size_t)NB * NV * NO];            // 64 MB: h = feat@W + b
__device__ __nv_bfloat16 g_Whi[(size_t)NV * NO * NI];  // 8 MB, layout [v][o][i]
__device__ __nv_bfloat16 g_Wlo[(size_t)NV * NO * NI];  // 8 MB
__device__ __nv_bfloat16 g_adjhi[NV * NV];
__device__ __nv_bfloat16 g_adjlo[NV * NV];
__device__ float g_sum[NV * NO];
__device__ float g_sqs[NV * NO];
__device__ float g_s[NV * NO];
__device__ float g_t[NV * NO];

// ---------------------------------------------------------------------------
// Helpers (baseline PTX only)
// ---------------------------------------------------------------------------
__device__ __forceinline__ uint32_t smem_u32(const void* p) {
    uint32_t a;
    asm("{ .reg .u64 t; cvta.to.shared.u64 t, %1; cvt.u32.u64 %0, t; }"
        : "=r"(a) : "l"(p));
    return a;
}
#define SWZ(off) ((uint32_t)(off) ^ ((((uint32_t)(off)) >> 3) & 0x70))

__device__ __forceinline__ void ldsm_x4(uint32_t* r, uint32_t addr) {
    asm volatile("ldmatrix.sync.aligned.m8n8.x4.shared.b16 {%0,%1,%2,%3}, [%4];"
                 : "=r"(r[0]), "=r"(r[1]), "=r"(r[2]), "=r"(r[3]) : "r"(addr));
}
__device__ __forceinline__ void ldsm_x2(uint32_t* r, uint32_t addr) {
    asm volatile("ldmatrix.sync.aligned.m8n8.x2.shared.b16 {%0,%1}, [%2];"
                 : "=r"(r[0]), "=r"(r[1]) : "r"(addr));
}
__device__ __forceinline__ void ldsm_x2t(uint32_t* r, uint32_t addr) {
    asm volatile("ldmatrix.sync.aligned.m8n8.x2.trans.shared.b16 {%0,%1}, [%2];"
                 : "=r"(r[0]), "=r"(r[1]) : "r"(addr));
}
__device__ __forceinline__ void mma_bf16(float* d, const uint32_t* a,
                                         const uint32_t* b) {
    asm volatile(
        "mma.sync.aligned.m16n8k16.row.col.f32.bf16.bf16.f32 "
        "{%0,%1,%2,%3}, {%4,%5,%6,%7}, {%8,%9}, {%0,%1,%2,%3};"
        : "+f"(d[0]), "+f"(d[1]), "+f"(d[2]), "+f"(d[3])
        : "r"(a[0]), "r"(a[1]), "r"(a[2]), "r"(a[3]), "r"(b[0]), "r"(b[1]));
}

// ---------------------------------------------------------------------------
// Kernel A: split W into bf16 hi/lo, transposed to K-major [v][o][i]
// ---------------------------------------------------------------------------
__global__ __launch_bounds__(256) void convert_W(const float* __restrict__ W) {
    __shared__ float tile[256][65];
    const int v = blockIdx.y, o0 = blockIdx.x * 64;
    const int t = threadIdx.x;
    const float* src = W + (size_t)v * NI * NO + o0;
#pragma unroll 8
    for (int r = 0; r < 64; r++) {
        int idx = r * 256 + t;
        int i = idx >> 6, o = idx & 63;
        tile[i][o] = src[(size_t)i * NO + o];
    }
    __syncthreads();
    __nv_bfloat16* dh = g_Whi + ((size_t)v * NO + o0) * NI;
    __nv_bfloat16* dl = g_Wlo + ((size_t)v * NO + o0) * NI;
#pragma unroll 8
    for (int r = 0; r < 64; r++) {
        float x = tile[t][r];
        __nv_bfloat16 hi = __float2bfloat16(x);
        __nv_bfloat16 lo = __float2bfloat16(x - __bfloat162float(hi));
        dh[(size_t)r * NI + t] = hi;
        dl[(size_t)r * NI + t] = lo;
    }
}

// ---------------------------------------------------------------------------
// Kernel A2: split adj into bf16 hi/lo AND zero the stats accumulators.
// grid 16 x 256.
// ---------------------------------------------------------------------------
__global__ void convert_adj(const float* __restrict__ adj) {
    int i = blockIdx.x * 256 + threadIdx.x;   // 0..4095
    float x = adj[i];
    __nv_bfloat16 hi = __float2bfloat16(x);
    g_adjhi[i] = hi;
    g_adjlo[i] = __float2bfloat16(x - __bfloat162float(hi));
    ((float4*)g_sum)[i] = make_float4(0.f, 0.f, 0.f, 0.f);
    ((float4*)g_sqs)[i] = make_float4(0.f, 0.f, 0.f, 0.f);
}

// ---------------------------------------------------------------------------
// Kernel B: mma.sync split-bf16 GEMM  h[m,v,:] = feat[m,v,:] @ W[v] + bias[v]
// + fused per-column sum/sumsq accumulation (BN stats).
// grid (NB/128, NO/128, NV), block 256 (8 warps), tile 128x128, K-chunks of 64
// ---------------------------------------------------------------------------
static constexpr int A_HI = 0;
static constexpr int A_LO = 16384;
static constexpr int B_HI = 32768;
static constexpr int B_LO = 49152;
static constexpr int GEMM_DSMEM = 65536 + 1024;

__global__ __launch_bounds__(256, 2) void gemm_mma(const float* __restrict__ feat,
                                                   const float* __restrict__ bias) {
    extern __shared__ char dynraw[];
    uint32_t rawa = smem_u32(dynraw);
    char* smb = dynraw + (((rawa + 1023) & ~1023u) - rawa);
    const uint32_t aHi = smem_u32(smb);

    const int v  = blockIdx.z;
    const int m0 = blockIdx.x * 128;
    const int n0 = blockIdx.y * 128;
    const int t  = threadIdx.x;
    const int lane = t & 31;
    const int w = t >> 5;
    const int mw = (w >> 2) * 64;
    const int nw = (w & 3) * 32;

    float acc[4][4][4];
#pragma unroll
    for (int i = 0; i < 4; i++)
#pragma unroll
        for (int j = 0; j < 4; j++)
#pragma unroll
            for (int q = 0; q < 4; q++) acc[i][j][q] = 0.f;

    const __nv_bfloat16* Wh = g_Whi + ((size_t)v * NO + n0) * NI;
    const __nv_bfloat16* Wl = g_Wlo + ((size_t)v * NO + n0) * NI;

    for (int c = 0; c < 4; c++) {
        const int k0 = c * 64;
        if (c) __syncthreads();

#pragma unroll
        for (int r = 0; r < 8; r++) {
            int idx = t + r * 256;
            int m = idx >> 4, kq = idx & 15;
            float4 x = *(const float4*)(feat +
                        ((size_t)(m0 + m) * NV + v) * NI + k0 + kq * 4);
            __nv_bfloat16 h0 = __float2bfloat16(x.x);
            __nv_bfloat16 h1 = __float2bfloat16(x.y);
            __nv_bfloat16 h2 = __float2bfloat16(x.z);
            __nv_bfloat16 h3 = __float2bfloat16(x.w);
            __nv_bfloat16 l0 = __float2bfloat16(x.x - __bfloat162float(h0));
            __nv_bfloat16 l1 = __float2bfloat16(x.y - __bfloat162float(h1));
            __nv_bfloat16 l2 = __float2bfloat16(x.z - __bfloat162float(h2));
            __nv_bfloat16 l3 = __float2bfloat16(x.w - __bfloat162float(h3));
            uint32_t off = SWZ(m * 128 + kq * 8);
            __nv_bfloat162 hp0 = {h0, h1}, hp1 = {h2, h3};
            __nv_bfloat162 lp0 = {l0, l1}, lp1 = {l2, l3};
            *(uint2*)(smb + A_HI + off) =
                make_uint2(*(uint32_t*)&hp0, *(uint32_t*)&hp1);
            *(uint2*)(smb + A_LO + off) =
                make_uint2(*(uint32_t*)&lp0, *(uint32_t*)&lp1);
        }
#pragma unroll
        for (int r = 0; r < 4; r++) {
            int idx = t + r * 256;
            int n = idx >> 3, kc = idx & 7;
            uint32_t off = SWZ(n * 128 + kc * 16);
            *(uint4*)(smb + B_HI + off) =
                *(const uint4*)(Wh + (size_t)n * NI + k0 + kc * 8);
            *(uint4*)(smb + B_LO + off) =
                *(const uint4*)(Wl + (size_t)n * NI + k0 + kc * 8);
        }
        __syncthreads();

#pragma unroll
        for (int ks = 0; ks < 4; ks++) {
            uint32_t bh[4][2], bl[4][2];
            {
                int brow = nw + (lane & 7);
                int bk = ks * 16 + ((lane >> 3) & 1) * 8;
#pragma unroll
                for (int nt = 0; nt < 4; nt++) {
                    uint32_t addr =
                        aHi + B_HI + SWZ((brow + nt * 8) * 128 + bk * 2);
                    ldsm_x2(bh[nt], addr);
                    ldsm_x2(bl[nt], addr + (B_LO - B_HI));
                }
            }
            int arow = mw + (lane & 7) + ((lane >> 3) & 1) * 8;
            int ak = ks * 16 + ((lane >> 4) & 1) * 8;
#pragma unroll
            for (int mt = 0; mt < 4; mt++) {
                uint32_t ra[4], rl[4];
                uint32_t addr = aHi + SWZ((arow + mt * 16) * 128 + ak * 2);
                ldsm_x4(ra, addr);
                ldsm_x4(rl, addr + A_LO);
#pragma unroll
                for (int nt = 0; nt < 4; nt++) {
                    mma_bf16(acc[mt][nt], ra, bh[nt]);
                    mma_bf16(acc[mt][nt], ra, bl[nt]);
                    mma_bf16(acc[mt][nt], rl, bh[nt]);
                }
            }
        }
    }

    // ---- epilogue: bias add + store h + fused column stats
    __syncthreads();                       // smem reads done; reuse as reducer
    float* s_sum = (float*)smb;            // [128]
    float* s_sq  = (float*)smb + 128;      // [128]
    if (t < 128) { s_sum[t] = 0.f; s_sq[t] = 0.f; }
    __syncthreads();

#pragma unroll
    for (int mt = 0; mt < 4; mt++) {
        int mlo = m0 + mw + mt * 16 + (lane >> 2);
#pragma unroll
        for (int nt = 0; nt < 4; nt++) {
            int nl = nw + nt * 8 + (lane & 3) * 2;     // col within block tile
            int n = n0 + nl;
            float2 bv = *(const float2*)(bias + v * NO + n);
            float2 o0, o1;
            o0.x = acc[mt][nt][0] + bv.x;
            o0.y = acc[mt][nt][1] + bv.y;
            o1.x = acc[mt][nt][2] + bv.x;
            o1.y = acc[mt][nt][3] + bv.y;
            *(float2*)(g_h + (size_t)mlo * (NV * NO) + v * NO + n) = o0;
            *(float2*)(g_h + (size_t)(mlo + 8) * (NV * NO) + v * NO + n) = o1;
            atomicAdd(&s_sum[nl],     o0.x + o1.x);
            atomicAdd(&s_sum[nl + 1], o0.y + o1.y);
            atomicAdd(&s_sq[nl],      fmaf(o0.x, o0.x, o1.x * o1.x));
            atomicAdd(&s_sq[nl + 1],  fmaf(o0.y, o0.y, o1.y * o1.y));
        }
    }
    __syncthreads();
    if (t < 128) {
        atomicAdd(&g_sum[v * NO + n0 + t], s_sum[t]);
        atomicAdd(&g_sqs[v * NO + n0 + t], s_sq[t]);
    }
}

// ---------------------------------------------------------------------------
// Kernel C: finalize BN fold:  s = gamma*rsqrt(var+eps), t = beta - mean*s
// grid 64 x 256 — one thread per (v,o) column.
// ---------------------------------------------------------------------------
__global__ __launch_bounds__(256) void stats_fin(const float* __restrict__ gamma,
                                                 const float* __restrict__ beta) {
    const int col = blockIdx.x * 256 + threadIdx.x;
    float mean = g_sum[col] * (1.f / NB);
    float var  = g_sqs[col] * (1.f / NB) - mean * mean;
    float s    = gamma[col] * rsqrtf(var + EPS);
    g_s[col] = s;
    g_t[col] = fmaf(-mean, s, beta[col]);
}

// ---------------------------------------------------------------------------
// Kernel D: tensorized mix (validated in R4: ~30us).
// out[b,u,o] = relu( sum_v adj[u,v] * (s[v,o]*h[b,v,o] + t[v,o]) )
// ---------------------------------------------------------------------------
static constexpr int OPAD = 264;
static constexpr int HS_HI = 0;
static constexpr int HS_LO = 33792;
static constexpr int ADJ_HI = 67584;
static constexpr int ADJ_LO = 76800;
static constexpr int MIX_DSMEM = 86016 + 1024;

__global__ __launch_bounds__(256, 2) void mix_tc(float* __restrict__ out) {
    extern __shared__ char dynraw[];
    uint32_t rawa = smem_u32(dynraw);
    char* smb = dynraw + (((rawa + 1023) & ~1023u) - rawa);
    const uint32_t sbase = smem_u32(smb);

    const int b = blockIdx.x;
    const int t = threadIdx.x;
    const int lane = t & 31;
    const int w = t >> 5;

    const float4* h4 = (const float4*)(g_h + (size_t)b * NV * NO);
    const float4* s4 = (const float4*)g_s;
    const float4* t4 = (const float4*)g_t;
#pragma unroll
    for (int r = 0; r < 16; r++) {
        int idx = t + r * 256;
        int v = idx >> 6, oq = idx & 63;
        float4 h = h4[idx], sv = s4[idx], tv = t4[idx];
        float x0 = fmaf(h.x, sv.x, tv.x);
        float x1 = fmaf(h.y, sv.y, tv.y);
        float x2 = fmaf(h.z, sv.z, tv.z);
        float x3 = fmaf(h.w, sv.w, tv.w);
        __nv_bfloat16 h0 = __float2bfloat16(x0);
        __nv_bfloat16 h1 = __float2bfloat16(x1);
        __nv_bfloat16 h2 = __float2bfloat16(x2);
        __nv_bfloat16 h3 = __float2bfloat16(x3);
        __nv_bfloat16 l0 = __float2bfloat16(x0 - __bfloat162float(h0));
        __nv_bfloat16 l1 = __float2bfloat16(x1 - __bfloat162float(h1));
        __nv_bfloat16 l2 = __float2bfloat16(x2 - __bfloat162float(h2));
        __nv_bfloat16 l3 = __float2bfloat16(x3 - __bfloat162float(h3));
        __nv_bfloat162 hp0 = {h0, h1}, hp1 = {h2, h3};
        __nv_bfloat162 lp0 = {l0, l1}, lp1 = {l2, l3};
        uint32_t off = (uint32_t)(v * (OPAD * 2) + oq * 8);
        *(uint2*)(smb + HS_HI + off) =
            make_uint2(*(uint32_t*)&hp0, *(uint32_t*)&hp1);
        *(uint2*)(smb + HS_LO + off) =
            make_uint2(*(uint32_t*)&lp0, *(uint32_t*)&lp1);
    }
#pragma unroll
    for (int r = 0; r < 8; r++) {
        int idx = t + r * 256;
        int u = idx >> 5, q = idx & 31;
        *(uint32_t*)(smb + ADJ_HI + u * 144 + q * 4) =
            ((const uint32_t*)g_adjhi)[idx];
        *(uint32_t*)(smb + ADJ_LO + u * 144 + q * 4) =
            ((const uint32_t*)g_adjlo)[idx];
    }
    __syncthreads();

    const int mw = (w >> 1) * 16;
    const int nw = (w & 1) * 128;

    float acc[16][4];
#pragma unroll
    for (int i = 0; i < 16; i++)
#pragma unroll
        for (int q = 0; q < 4; q++) acc[i][q] = 0.f;

#pragma unroll
    for (int ks = 0; ks < 4; ks++) {
        uint32_t ah[4], al[4];
        uint32_t aaddr = sbase + ADJ_HI + (mw + (lane & 15)) * 144 +
                         (ks * 16 + (lane >> 4) * 8) * 2;
        ldsm_x4(ah, aaddr);
        ldsm_x4(al, aaddr + (ADJ_LO - ADJ_HI));

        uint32_t brow = sbase + HS_HI + (ks * 16 + (lane & 15)) * (OPAD * 2);
#pragma unroll
        for (int nt = 0; nt < 16; nt++) {
            int n0 = nw + nt * 8;
            uint32_t bh[2], bl[2];
            ldsm_x2t(bh, brow + n0 * 2);
            ldsm_x2t(bl, brow + n0 * 2 + (HS_LO - HS_HI));
            mma_bf16(acc[nt], ah, bh);
            mma_bf16(acc[nt], ah, bl);
            mma_bf16(acc[nt], al, bh);
        }
    }

    float* ob = out + (size_t)b * NV * NO;
    const int u0 = mw + (lane >> 2);
#pragma unroll
    for (int nt = 0; nt < 16; nt++) {
        int o = nw + nt * 8 + (lane & 3) * 2;
        float2 r0, r1;
        r0.x = fmaxf(acc[nt][0], 0.f);
        r0.y = fmaxf(acc[nt][1], 0.f);
        r1.x = fmaxf(acc[nt][2], 0.f);
        r1.y = fmaxf(acc[nt][3], 0.f);
        *(float2*)(ob + (size_t)u0 * NO + o) = r0;
        *(float2*)(ob + (size_t)(u0 + 8) * NO + o) = r1;
    }
}

// ---------------------------------------------------------------------------
extern "C" void kernel_launch(void* const* d_in, const int* in_sizes, int n_in,
                              void* d_out, int out_size) {
    const float* feat  = (const float*)d_in[0];
    const float* adj   = (const float*)d_in[1];
    const float* W     = (const float*)d_in[2];
    const float* bias  = (const float*)d_in[3];
    const float* gamma = (const float*)d_in[4];
    const float* beta  = (const float*)d_in[5];
    float* out = (float*)d_out;

    cudaFuncSetAttribute(gemm_mma, cudaFuncAttributeMaxDynamicSharedMemorySize,
                         GEMM_DSMEM);
    cudaFuncSetAttribute(mix_tc, cudaFuncAttributeMaxDynamicSharedMemorySize,
                         MIX_DSMEM);

    convert_W<<<dim3(NO / 64, NV), 256>>>(W);
    convert_adj<<<16, 256>>>(adj);   // also zeroes g_sum/g_sqs
    gemm_mma<<<dim3(NB / 128, NO / 128, NV), 256, GEMM_DSMEM>>>(feat, bias);
    stats_fin<<<64, 256>>>(gamma, beta);
    mix_tc<<<NB, 256, MIX_DSMEM>>>(out);
}

// round 6
// speedup vs baseline: 1.4420x; 1.4338x over previous
#include <cuda_runtime.h>
#include <cuda_bf16.h>
#include <cstdint>

#define NB 1024
#define NV 64
#define NI 256
#define NO 256
constexpr float EPS = 1e-5f;

// ---------------------------------------------------------------------------
// Device scratch
// ---------------------------------------------------------------------------
__device__ float g_h[(size_t)NB * NV * NO];            // 64 MB: h = feat@W + b
__device__ __nv_bfloat16 g_Whi[(size_t)NV * NO * NI];  // 8 MB, layout [v][o][i]
__device__ __nv_bfloat16 g_Wlo[(size_t)NV * NO * NI];  // 8 MB
__device__ __nv_bfloat16 g_adjhi[NV * NV];
__device__ __nv_bfloat16 g_adjlo[NV * NV];
__device__ float g_sum[NV * NO];
__device__ float g_sqs[NV * NO];
__device__ float g_s[NV * NO];
__device__ float g_t[NV * NO];

// ---------------------------------------------------------------------------
// Helpers (baseline PTX only)
// ---------------------------------------------------------------------------
__device__ __forceinline__ uint32_t smem_u32(const void* p) {
    uint32_t a;
    asm("{ .reg .u64 t; cvta.to.shared.u64 t, %1; cvt.u32.u64 %0, t; }"
        : "=r"(a) : "l"(p));
    return a;
}
#define SWZ(off) ((uint32_t)(off) ^ ((((uint32_t)(off)) >> 3) & 0x70))

__device__ __forceinline__ void ldsm_x4(uint32_t* r, uint32_t addr) {
    asm volatile("ldmatrix.sync.aligned.m8n8.x4.shared.b16 {%0,%1,%2,%3}, [%4];"
                 : "=r"(r[0]), "=r"(r[1]), "=r"(r[2]), "=r"(r[3]) : "r"(addr));
}
__device__ __forceinline__ void ldsm_x2(uint32_t* r, uint32_t addr) {
    asm volatile("ldmatrix.sync.aligned.m8n8.x2.shared.b16 {%0,%1}, [%2];"
                 : "=r"(r[0]), "=r"(r[1]) : "r"(addr));
}
__device__ __forceinline__ void ldsm_x2t(uint32_t* r, uint32_t addr) {
    asm volatile("ldmatrix.sync.aligned.m8n8.x2.trans.shared.b16 {%0,%1}, [%2];"
                 : "=r"(r[0]), "=r"(r[1]) : "r"(addr));
}
__device__ __forceinline__ void mma_bf16(float* d, const uint32_t* a,
                                         const uint32_t* b) {
    asm volatile(
        "mma.sync.aligned.m16n8k16.row.col.f32.bf16.bf16.f32 "
        "{%0,%1,%2,%3}, {%4,%5,%6,%7}, {%8,%9}, {%0,%1,%2,%3};"
        : "+f"(d[0]), "+f"(d[1]), "+f"(d[2]), "+f"(d[3])
        : "r"(a[0]), "r"(a[1]), "r"(a[2]), "r"(a[3]), "r"(b[0]), "r"(b[1]));
}
__device__ __forceinline__ void cp16(uint32_t smem, const void* g) {
    asm volatile("cp.async.cg.shared.global [%0], [%1], 16;"
                 :: "r"(smem), "l"(g) : "memory");
}
#define CP_COMMIT() asm volatile("cp.async.commit_group;" ::: "memory")
#define CP_WAIT(N)  asm volatile("cp.async.wait_group %0;" :: "n"(N) : "memory")

// ---------------------------------------------------------------------------
// Kernel A: split W into bf16 hi/lo, transposed to K-major [v][o][i]
// ---------------------------------------------------------------------------
__global__ __launch_bounds__(256) void convert_W(const float* __restrict__ W) {
    __shared__ float tile[256][65];
    const int v = blockIdx.y, o0 = blockIdx.x * 64;
    const int t = threadIdx.x;
    const float* src = W + (size_t)v * NI * NO + o0;
#pragma unroll 8
    for (int r = 0; r < 64; r++) {
        int idx = r * 256 + t;
        int i = idx >> 6, o = idx & 63;
        tile[i][o] = src[(size_t)i * NO + o];
    }
    __syncthreads();
    __nv_bfloat16* dh = g_Whi + ((size_t)v * NO + o0) * NI;
    __nv_bfloat16* dl = g_Wlo + ((size_t)v * NO + o0) * NI;
#pragma unroll 8
    for (int r = 0; r < 64; r++) {
        float x = tile[t][r];
        __nv_bfloat16 hi = __float2bfloat16(x);
        __nv_bfloat16 lo = __float2bfloat16(x - __bfloat162float(hi));
        dh[(size_t)r * NI + t] = hi;
        dl[(size_t)r * NI + t] = lo;
    }
}

// ---------------------------------------------------------------------------
// Kernel A2: split adj into bf16 hi/lo AND zero stats accumulators.
// ---------------------------------------------------------------------------
__global__ void convert_adj(const float* __restrict__ adj) {
    int i = blockIdx.x * 256 + threadIdx.x;   // 0..4095
    float x = adj[i];
    __nv_bfloat16 hi = __float2bfloat16(x);
    g_adjhi[i] = hi;
    g_adjlo[i] = __float2bfloat16(x - __bfloat162float(hi));
    ((float4*)g_sum)[i] = make_float4(0.f, 0.f, 0.f, 0.f);
    ((float4*)g_sqs)[i] = make_float4(0.f, 0.f, 0.f, 0.f);
}

// ---------------------------------------------------------------------------
// Kernel B: pipelined mma.sync split-bf16 GEMM + shuffle-reduced BN stats.
// grid (NB/128, NO/128, NV), block 256 (8 warps), tile 128x128,
// K-chunks of 64, 2-stage cp.async double buffer (B via cp.async,
// A via register-prefetch LDG + cvt/STS).
// ---------------------------------------------------------------------------
static constexpr int A_HI = 0;
static constexpr int A_LO = 16384;
static constexpr int B_HI = 32768;
static constexpr int B_LO = 49152;
static constexpr int STAGE = 65536;
static constexpr int GEMM_DSMEM = 2 * STAGE + 1024;

__device__ __forceinline__ void load_A_regs(float4* areg,
                                            const float* __restrict__ feat,
                                            int m0, int v, int k0, int t) {
#pragma unroll
    for (int r = 0; r < 8; r++) {
        int idx = t + r * 256;
        int m = idx >> 4, kq = idx & 15;
        areg[r] = *(const float4*)(feat +
                   ((size_t)(m0 + m) * NV + v) * NI + k0 + kq * 4);
    }
}
__device__ __forceinline__ void store_A_smem(char* buf, const float4* areg,
                                             int t) {
#pragma unroll
    for (int r = 0; r < 8; r++) {
        int idx = t + r * 256;
        int m = idx >> 4, kq = idx & 15;
        float4 x = areg[r];
        __nv_bfloat16 h0 = __float2bfloat16(x.x);
        __nv_bfloat16 h1 = __float2bfloat16(x.y);
        __nv_bfloat16 h2 = __float2bfloat16(x.z);
        __nv_bfloat16 h3 = __float2bfloat16(x.w);
        __nv_bfloat16 l0 = __float2bfloat16(x.x - __bfloat162float(h0));
        __nv_bfloat16 l1 = __float2bfloat16(x.y - __bfloat162float(h1));
        __nv_bfloat16 l2 = __float2bfloat16(x.z - __bfloat162float(h2));
        __nv_bfloat16 l3 = __float2bfloat16(x.w - __bfloat162float(h3));
        uint32_t off = SWZ(m * 128 + kq * 8);
        __nv_bfloat162 hp0 = {h0, h1}, hp1 = {h2, h3};
        __nv_bfloat162 lp0 = {l0, l1}, lp1 = {l2, l3};
        *(uint2*)(buf + A_HI + off) =
            make_uint2(*(uint32_t*)&hp0, *(uint32_t*)&hp1);
        *(uint2*)(buf + A_LO + off) =
            make_uint2(*(uint32_t*)&lp0, *(uint32_t*)&lp1);
    }
}
__device__ __forceinline__ void issue_B(uint32_t sb,
                                        const __nv_bfloat16* __restrict__ Wh,
                                        const __nv_bfloat16* __restrict__ Wl,
                                        int k0, int t) {
#pragma unroll
    for (int r = 0; r < 4; r++) {
        int idx = t + r * 256;
        int n = idx >> 3, kc = idx & 7;
        uint32_t off = SWZ(n * 128 + kc * 16);
        cp16(sb + B_HI + off, Wh + (size_t)n * NI + k0 + kc * 8);
        cp16(sb + B_LO + off, Wl + (size_t)n * NI + k0 + kc * 8);
    }
}

__global__ __launch_bounds__(256, 1) void gemm_mma(const float* __restrict__ feat,
                                                   const float* __restrict__ bias) {
    extern __shared__ char dynraw[];
    uint32_t rawa = smem_u32(dynraw);
    char* smb = dynraw + (((rawa + 1023) & ~1023u) - rawa);
    const uint32_t sbase = smem_u32(smb);

    const int v  = blockIdx.z;
    const int m0 = blockIdx.x * 128;
    const int n0 = blockIdx.y * 128;
    const int t  = threadIdx.x;
    const int lane = t & 31;
    const int w = t >> 5;
    const int mw = (w >> 2) * 64;
    const int nw = (w & 3) * 32;

    float acc[4][4][4];
#pragma unroll
    for (int i = 0; i < 4; i++)
#pragma unroll
        for (int j = 0; j < 4; j++)
#pragma unroll
            for (int q = 0; q < 4; q++) acc[i][j][q] = 0.f;

    const __nv_bfloat16* Wh = g_Whi + ((size_t)v * NO + n0) * NI;
    const __nv_bfloat16* Wl = g_Wlo + ((size_t)v * NO + n0) * NI;

    // ---- prologue: A regs chunk 0, cp.async B chunk 0
    float4 areg[8];
    load_A_regs(areg, feat, m0, v, 0, t);
    issue_B(sbase, Wh, Wl, 0, t);
    CP_COMMIT();

#pragma unroll
    for (int c = 0; c < 4; c++) {
        char* buf = smb + (c & 1) * STAGE;
        const uint32_t sb = sbase + (c & 1) * STAGE;

        store_A_smem(buf, areg, t);
        if (c < 3) {
            load_A_regs(areg, feat, m0, v, (c + 1) * 64, t);  // prefetch
            issue_B(sbase + ((c + 1) & 1) * STAGE, Wh, Wl, (c + 1) * 64, t);
            CP_COMMIT();
            CP_WAIT(1);
        } else {
            CP_WAIT(0);
        }
        __syncthreads();

#pragma unroll
        for (int ks = 0; ks < 4; ks++) {
            uint32_t bh[4][2], bl[4][2];
            {
                int brow = nw + (lane & 7);
                int bk = ks * 16 + ((lane >> 3) & 1) * 8;
#pragma unroll
                for (int nt = 0; nt < 4; nt++) {
                    uint32_t addr = sb + B_HI + SWZ((brow + nt * 8) * 128 + bk * 2);
                    ldsm_x2(bh[nt], addr);
                    ldsm_x2(bl[nt], addr + (B_LO - B_HI));
                }
            }
            int arow = mw + (lane & 7) + ((lane >> 3) & 1) * 8;
            int ak = ks * 16 + ((lane >> 4) & 1) * 8;
#pragma unroll
            for (int mt = 0; mt < 4; mt++) {
                uint32_t ra[4], rl[4];
                uint32_t addr = sb + A_HI + SWZ((arow + mt * 16) * 128 + ak * 2);
                ldsm_x4(ra, addr);
                ldsm_x4(rl, addr + (A_LO - A_HI));
#pragma unroll
                for (int nt = 0; nt < 4; nt++) {
                    mma_bf16(acc[mt][nt], ra, bh[nt]);
                    mma_bf16(acc[mt][nt], ra, bl[nt]);
                    mma_bf16(acc[mt][nt], rl, bh[nt]);
                }
            }
        }
        if (c < 3) __syncthreads();
    }

    // ---- epilogue: bias + store h + shuffle-reduced column stats
#pragma unroll
    for (int nt = 0; nt < 4; nt++) {
        const int nl = nw + nt * 8 + (lane & 3) * 2;   // col in block tile
        const int n = n0 + nl;
        float2 bv = *(const float2*)(bias + v * NO + n);
        float2 sum2 = make_float2(0.f, 0.f), sq2 = make_float2(0.f, 0.f);
#pragma unroll
        for (int mt = 0; mt < 4; mt++) {
            int mlo = m0 + mw + mt * 16 + (lane >> 2);
            float2 o0, o1;
            o0.x = acc[mt][nt][0] + bv.x;
            o0.y = acc[mt][nt][1] + bv.y;
            o1.x = acc[mt][nt][2] + bv.x;
            o1.y = acc[mt][nt][3] + bv.y;
            *(float2*)(g_h + (size_t)mlo * (NV * NO) + v * NO + n) = o0;
            *(float2*)(g_h + (size_t)(mlo + 8) * (NV * NO) + v * NO + n) = o1;
            sum2.x += o0.x + o1.x;
            sum2.y += o0.y + o1.y;
            sq2.x += fmaf(o0.x, o0.x, o1.x * o1.x);
            sq2.y += fmaf(o0.y, o0.y, o1.y * o1.y);
        }
        // reduce across the 8 lanes sharing these columns (bits 2..4 of lane)
#pragma unroll
        for (int msk = 4; msk <= 16; msk <<= 1) {
            sum2.x += __shfl_xor_sync(0xffffffffu, sum2.x, msk);
            sum2.y += __shfl_xor_sync(0xffffffffu, sum2.y, msk);
            sq2.x  += __shfl_xor_sync(0xffffffffu, sq2.x, msk);
            sq2.y  += __shfl_xor_sync(0xffffffffu, sq2.y, msk);
        }
        if (lane < 4) {
            atomicAdd(&g_sum[v * NO + n],     sum2.x);
            atomicAdd(&g_sum[v * NO + n + 1], sum2.y);
            atomicAdd(&g_sqs[v * NO + n],     sq2.x);
            atomicAdd(&g_sqs[v * NO + n + 1], sq2.y);
        }
    }
}

// ---------------------------------------------------------------------------
// Kernel C: finalize BN fold
// ---------------------------------------------------------------------------
__global__ __launch_bounds__(256) void stats_fin(const float* __restrict__ gamma,
                                                 const float* __restrict__ beta) {
    const int col = blockIdx.x * 256 + threadIdx.x;
    float mean = g_sum[col] * (1.f / NB);
    float var  = g_sqs[col] * (1.f / NB) - mean * mean;
    float s    = gamma[col] * rsqrtf(var + EPS);
    g_s[col] = s;
    g_t[col] = fmaf(-mean, s, beta[col]);
}

// ---------------------------------------------------------------------------
// Kernel D: tensorized mix (validated ~30us in R4/R5)
// ---------------------------------------------------------------------------
static constexpr int OPAD = 264;
static constexpr int HS_HI = 0;
static constexpr int HS_LO = 33792;
static constexpr int ADJ_HI = 67584;
static constexpr int ADJ_LO = 76800;
static constexpr int MIX_DSMEM = 86016 + 1024;

__global__ __launch_bounds__(256, 2) void mix_tc(float* __restrict__ out) {
    extern __shared__ char dynraw[];
    uint32_t rawa = smem_u32(dynraw);
    char* smb = dynraw + (((rawa + 1023) & ~1023u) - rawa);
    const uint32_t sbase = smem_u32(smb);

    const int b = blockIdx.x;
    const int t = threadIdx.x;
    const int lane = t & 31;
    const int w = t >> 5;

    const float4* h4 = (const float4*)(g_h + (size_t)b * NV * NO);
    const float4* s4 = (const float4*)g_s;
    const float4* t4 = (const float4*)g_t;
#pragma unroll
    for (int r = 0; r < 16; r++) {
        int idx = t + r * 256;
        int v = idx >> 6, oq = idx & 63;
        float4 h = h4[idx], sv = s4[idx], tv = t4[idx];
        float x0 = fmaf(h.x, sv.x, tv.x);
        float x1 = fmaf(h.y, sv.y, tv.y);
        float x2 = fmaf(h.z, sv.z, tv.z);
        float x3 = fmaf(h.w, sv.w, tv.w);
        __nv_bfloat16 h0 = __float2bfloat16(x0);
        __nv_bfloat16 h1 = __float2bfloat16(x1);
        __nv_bfloat16 h2 = __float2bfloat16(x2);
        __nv_bfloat16 h3 = __float2bfloat16(x3);
        __nv_bfloat16 l0 = __float2bfloat16(x0 - __bfloat162float(h0));
        __nv_bfloat16 l1 = __float2bfloat16(x1 - __bfloat162float(h1));
        __nv_bfloat16 l2 = __float2bfloat16(x2 - __bfloat162float(h2));
        __nv_bfloat16 l3 = __float2bfloat16(x3 - __bfloat162float(h3));
        __nv_bfloat162 hp0 = {h0, h1}, hp1 = {h2, h3};
        __nv_bfloat162 lp0 = {l0, l1}, lp1 = {l2, l3};
        uint32_t off = (uint32_t)(v * (OPAD * 2) + oq * 8);
        *(uint2*)(smb + HS_HI + off) =
            make_uint2(*(uint32_t*)&hp0, *(uint32_t*)&hp1);
        *(uint2*)(smb + HS_LO + off) =
            make_uint2(*(uint32_t*)&lp0, *(uint32_t*)&lp1);
    }
#pragma unroll
    for (int r = 0; r < 8; r++) {
        int idx = t + r * 256;
        int u = idx >> 5, q = idx & 31;
        *(uint32_t*)(smb + ADJ_HI + u * 144 + q * 4) =
            ((const uint32_t*)g_adjhi)[idx];
        *(uint32_t*)(smb + ADJ_LO + u * 144 + q * 4) =
            ((const uint32_t*)g_adjlo)[idx];
    }
    __syncthreads();

    const int mw = (w >> 1) * 16;
    const int nw = (w & 1) * 128;

    float acc[16][4];
#pragma unroll
    for (int i = 0; i < 16; i++)
#pragma unroll
        for (int q = 0; q < 4; q++) acc[i][q] = 0.f;

#pragma unroll
    for (int ks = 0; ks < 4; ks++) {
        uint32_t ah[4], al[4];
        uint32_t aaddr = sbase + ADJ_HI + (mw + (lane & 15)) * 144 +
                         (ks * 16 + (lane >> 4) * 8) * 2;
        ldsm_x4(ah, aaddr);
        ldsm_x4(al, aaddr + (ADJ_LO - ADJ_HI));

        uint32_t brow = sbase + HS_HI + (ks * 16 + (lane & 15)) * (OPAD * 2);
#pragma unroll
        for (int nt = 0; nt < 16; nt++) {
            int n0 = nw + nt * 8;
            uint32_t bh[2], bl[2];
            ldsm_x2t(bh, brow + n0 * 2);
            ldsm_x2t(bl, brow + n0 * 2 + (HS_LO - HS_HI));
            mma_bf16(acc[nt], ah, bh);
            mma_bf16(acc[nt], ah, bl);
            mma_bf16(acc[nt], al, bh);
        }
    }

    float* ob = out + (size_t)b * NV * NO;
    const int u0 = mw + (lane >> 2);
#pragma unroll
    for (int nt = 0; nt < 16; nt++) {
        int o = nw + nt * 8 + (lane & 3) * 2;
        float2 r0, r1;
        r0.x = fmaxf(acc[nt][0], 0.f);
        r0.y = fmaxf(acc[nt][1], 0.f);
        r1.x = fmaxf(acc[nt][2], 0.f);
        r1.y = fmaxf(acc[nt][3], 0.f);
        *(float2*)(ob + (size_t)u0 * NO + o) = r0;
        *(float2*)(ob + (size_t)(u0 + 8) * NO + o) = r1;
    }
}

// ---------------------------------------------------------------------------
extern "C" void kernel_launch(void* const* d_in, const int* in_sizes, int n_in,
                              void* d_out, int out_size) {
    const float* feat  = (const float*)d_in[0];
    const float* adj   = (const float*)d_in[1];
    const float* W     = (const float*)d_in[2];
    const float* bias  = (const float*)d_in[3];
    const float* gamma = (const float*)d_in[4];
    const float* beta  = (const float*)d_in[5];
    float* out = (float*)d_out;

    cudaFuncSetAttribute(gemm_mma, cudaFuncAttributeMaxDynamicSharedMemorySize,
                         GEMM_DSMEM);
    cudaFuncSetAttribute(mix_tc, cudaFuncAttributeMaxDynamicSharedMemorySize,
                         MIX_DSMEM);

    convert_W<<<dim3(NO / 64, NV), 256>>>(W);
    convert_adj<<<16, 256>>>(adj);   // also zeroes g_sum/g_sqs
    gemm_mma<<<dim3(NB / 128, NO / 128, NV), 256, GEMM_DSMEM>>>(feat, bias);
    stats_fin<<<64, 256>>>(gamma, beta);
    mix_tc<<<NB, 256, MIX_DSMEM>>>(out);
}

// round 7
// speedup vs baseline: 2.0374x; 1.4129x over previous
#include <cuda_runtime.h>
#include <cuda_bf16.h>
#include <cstdint>

#define NB 1024
#define NV 64
#define NI 256
#define NO 256
constexpr float EPS = 1e-5f;

// ---------------------------------------------------------------------------
// Device scratch
// ---------------------------------------------------------------------------
__device__ float g_h[(size_t)NB * NV * NO];            // 64 MB: h = feat@W + b
__device__ __nv_bfloat16 g_Whi[(size_t)NV * NO * NI];  // 8 MB, layout [v][o][i]
__device__ __nv_bfloat16 g_Wlo[(size_t)NV * NO * NI];  // 8 MB
__device__ __nv_bfloat16 g_adjhi[NV * NV];
__device__ __nv_bfloat16 g_adjlo[NV * NV];
__device__ float g_sum[NV * NO];
__device__ float g_sqs[NV * NO];
__device__ float g_s[NV * NO];
__device__ float g_t[NV * NO];

// ---------------------------------------------------------------------------
// Helpers (baseline PTX only)
// ---------------------------------------------------------------------------
__device__ __forceinline__ uint32_t smem_u32(const void* p) {
    uint32_t a;
    asm("{ .reg .u64 t; cvta.to.shared.u64 t, %1; cvt.u32.u64 %0, t; }"
        : "=r"(a) : "l"(p));
    return a;
}
#define SWZ(off) ((uint32_t)(off) ^ ((((uint32_t)(off)) >> 3) & 0x70))

__device__ __forceinline__ void ldsm_x4(uint32_t* r, uint32_t addr) {
    asm volatile("ldmatrix.sync.aligned.m8n8.x4.shared.b16 {%0,%1,%2,%3}, [%4];"
                 : "=r"(r[0]), "=r"(r[1]), "=r"(r[2]), "=r"(r[3]) : "r"(addr));
}
__device__ __forceinline__ void ldsm_x2(uint32_t* r, uint32_t addr) {
    asm volatile("ldmatrix.sync.aligned.m8n8.x2.shared.b16 {%0,%1}, [%2];"
                 : "=r"(r[0]), "=r"(r[1]) : "r"(addr));
}
__device__ __forceinline__ void ldsm_x2t(uint32_t* r, uint32_t addr) {
    asm volatile("ldmatrix.sync.aligned.m8n8.x2.trans.shared.b16 {%0,%1}, [%2];"
                 : "=r"(r[0]), "=r"(r[1]) : "r"(addr));
}
__device__ __forceinline__ void mma_bf16(float* d, const uint32_t* a,
                                         const uint32_t* b) {
    asm volatile(
        "mma.sync.aligned.m16n8k16.row.col.f32.bf16.bf16.f32 "
        "{%0,%1,%2,%3}, {%4,%5,%6,%7}, {%8,%9}, {%0,%1,%2,%3};"
        : "+f"(d[0]), "+f"(d[1]), "+f"(d[2]), "+f"(d[3])
        : "r"(a[0]), "r"(a[1]), "r"(a[2]), "r"(a[3]), "r"(b[0]), "r"(b[1]));
}
__device__ __forceinline__ void cp16(uint32_t smem, const void* g) {
    asm volatile("cp.async.cg.shared.global [%0], [%1], 16;"
                 :: "r"(smem), "l"(g) : "memory");
}
#define CP_COMMIT() asm volatile("cp.async.commit_group;" ::: "memory")
#define CP_WAIT(N)  asm volatile("cp.async.wait_group %0;" :: "n"(N) : "memory")

// ---------------------------------------------------------------------------
// Kernel A: split W into bf16 hi/lo, transposed to K-major [v][o][i]
// ---------------------------------------------------------------------------
__global__ __launch_bounds__(256) void convert_W(const float* __restrict__ W) {
    __shared__ float tile[256][65];
    const int v = blockIdx.y, o0 = blockIdx.x * 64;
    const int t = threadIdx.x;
    const float* src = W + (size_t)v * NI * NO + o0;
#pragma unroll 8
    for (int r = 0; r < 64; r++) {
        int idx = r * 256 + t;
        int i = idx >> 6, o = idx & 63;
        tile[i][o] = src[(size_t)i * NO + o];
    }
    __syncthreads();
    __nv_bfloat16* dh = g_Whi + ((size_t)v * NO + o0) * NI;
    __nv_bfloat16* dl = g_Wlo + ((size_t)v * NO + o0) * NI;
#pragma unroll 8
    for (int r = 0; r < 64; r++) {
        float x = tile[t][r];
        __nv_bfloat16 hi = __float2bfloat16(x);
        __nv_bfloat16 lo = __float2bfloat16(x - __bfloat162float(hi));
        dh[(size_t)r * NI + t] = hi;
        dl[(size_t)r * NI + t] = lo;
    }
}

// ---------------------------------------------------------------------------
// Kernel A2: split adj into bf16 hi/lo AND zero stats accumulators.
// ---------------------------------------------------------------------------
__global__ void convert_adj(const float* __restrict__ adj) {
    int i = blockIdx.x * 256 + threadIdx.x;   // 0..4095
    float x = adj[i];
    __nv_bfloat16 hi = __float2bfloat16(x);
    g_adjhi[i] = hi;
    g_adjlo[i] = __float2bfloat16(x - __bfloat162float(hi));
    ((float4*)g_sum)[i] = make_float4(0.f, 0.f, 0.f, 0.f);
    ((float4*)g_sqs)[i] = make_float4(0.f, 0.f, 0.f, 0.f);
}

// ---------------------------------------------------------------------------
// Kernel B: mma.sync split-bf16 GEMM + shuffle-reduced BN stats.
// grid (NB/128, NO/128, NV), block 256 (8 warps), tile 128x128, K-chunk 64.
// SINGLE 64KB stage -> 2 CTAs/SM (cross-CTA overlap), A reg-prefetch,
// B via cp.async.
// ---------------------------------------------------------------------------
static constexpr int A_HI = 0;
static constexpr int A_LO = 16384;
static constexpr int B_HI = 32768;
static constexpr int B_LO = 49152;
static constexpr int GEMM_DSMEM = 65536 + 1024;

__device__ __forceinline__ void load_A_regs(float4* areg,
                                            const float* __restrict__ feat,
                                            int m0, int v, int k0, int t) {
#pragma unroll
    for (int r = 0; r < 8; r++) {
        int idx = t + r * 256;
        int m = idx >> 4, kq = idx & 15;
        areg[r] = *(const float4*)(feat +
                   ((size_t)(m0 + m) * NV + v) * NI + k0 + kq * 4);
    }
}
__device__ __forceinline__ void store_A_smem(char* buf, const float4* areg,
                                             int t) {
#pragma unroll
    for (int r = 0; r < 8; r++) {
        int idx = t + r * 256;
        int m = idx >> 4, kq = idx & 15;
        float4 x = areg[r];
        __nv_bfloat16 h0 = __float2bfloat16(x.x);
        __nv_bfloat16 h1 = __float2bfloat16(x.y);
        __nv_bfloat16 h2 = __float2bfloat16(x.z);
        __nv_bfloat16 h3 = __float2bfloat16(x.w);
        __nv_bfloat16 l0 = __float2bfloat16(x.x - __bfloat162float(h0));
        __nv_bfloat16 l1 = __float2bfloat16(x.y - __bfloat162float(h1));
        __nv_bfloat16 l2 = __float2bfloat16(x.z - __bfloat162float(h2));
        __nv_bfloat16 l3 = __float2bfloat16(x.w - __bfloat162float(h3));
        uint32_t off = SWZ(m * 128 + kq * 8);
        __nv_bfloat162 hp0 = {h0, h1}, hp1 = {h2, h3};
        __nv_bfloat162 lp0 = {l0, l1}, lp1 = {l2, l3};
        *(uint2*)(buf + A_HI + off) =
            make_uint2(*(uint32_t*)&hp0, *(uint32_t*)&hp1);
        *(uint2*)(buf + A_LO + off) =
            make_uint2(*(uint32_t*)&lp0, *(uint32_t*)&lp1);
    }
}
__device__ __forceinline__ void issue_B(uint32_t sb,
                                        const __nv_bfloat16* __restrict__ Wh,
                                        const __nv_bfloat16* __restrict__ Wl,
                                        int k0, int t) {
#pragma unroll
    for (int r = 0; r < 4; r++) {
        int idx = t + r * 256;
        int n = idx >> 3, kc = idx & 7;
        uint32_t off = SWZ(n * 128 + kc * 16);
        cp16(sb + B_HI + off, Wh + (size_t)n * NI + k0 + kc * 8);
        cp16(sb + B_LO + off, Wl + (size_t)n * NI + k0 + kc * 8);
    }
}

__global__ __launch_bounds__(256, 2) void gemm_mma(const float* __restrict__ feat,
                                                   const float* __restrict__ bias) {
    extern __shared__ char dynraw[];
    uint32_t rawa = smem_u32(dynraw);
    char* smb = dynraw + (((rawa + 1023) & ~1023u) - rawa);
    const uint32_t sb = smem_u32(smb);

    const int v  = blockIdx.z;
    const int m0 = blockIdx.x * 128;
    const int n0 = blockIdx.y * 128;
    const int t  = threadIdx.x;
    const int lane = t & 31;
    const int w = t >> 5;
    const int mw = (w >> 2) * 64;
    const int nw = (w & 3) * 32;

    float acc[4][4][4];
#pragma unroll
    for (int i = 0; i < 4; i++)
#pragma unroll
        for (int j = 0; j < 4; j++)
#pragma unroll
            for (int q = 0; q < 4; q++) acc[i][j][q] = 0.f;

    const __nv_bfloat16* Wh = g_Whi + ((size_t)v * NO + n0) * NI;
    const __nv_bfloat16* Wl = g_Wlo + ((size_t)v * NO + n0) * NI;

    float4 areg[8];
    load_A_regs(areg, feat, m0, v, 0, t);

#pragma unroll
    for (int c = 0; c < 4; c++) {
        if (c) __syncthreads();            // prev chunk consumers done
        issue_B(sb, Wh, Wl, c * 64, t);    // cp.async into the single stage
        CP_COMMIT();
        store_A_smem(smb, areg, t);        // cvt+STS overlaps cp.async
        if (c < 3) load_A_regs(areg, feat, m0, v, (c + 1) * 64, t);  // prefetch
        CP_WAIT(0);
        __syncthreads();

#pragma unroll
        for (int ks = 0; ks < 4; ks++) {
            uint32_t bh[4][2], bl[4][2];
            {
                int brow = nw + (lane & 7);
                int bk = ks * 16 + ((lane >> 3) & 1) * 8;
#pragma unroll
                for (int nt = 0; nt < 4; nt++) {
                    uint32_t addr = sb + B_HI + SWZ((brow + nt * 8) * 128 + bk * 2);
                    ldsm_x2(bh[nt], addr);
                    ldsm_x2(bl[nt], addr + (B_LO - B_HI));
                }
            }
            int arow = mw + (lane & 7) + ((lane >> 3) & 1) * 8;
            int ak = ks * 16 + ((lane >> 4) & 1) * 8;
#pragma unroll
            for (int mt = 0; mt < 4; mt++) {
                uint32_t ra[4], rl[4];
                uint32_t addr = sb + A_HI + SWZ((arow + mt * 16) * 128 + ak * 2);
                ldsm_x4(ra, addr);
                ldsm_x4(rl, addr + (A_LO - A_HI));
#pragma unroll
                for (int nt = 0; nt < 4; nt++) {
                    mma_bf16(acc[mt][nt], ra, bh[nt]);
                    mma_bf16(acc[mt][nt], ra, bl[nt]);
                    mma_bf16(acc[mt][nt], rl, bh[nt]);
                }
            }
        }
    }

    // ---- epilogue: bias + store h + shuffle-reduced column stats
#pragma unroll
    for (int nt = 0; nt < 4; nt++) {
        const int nl = nw + nt * 8 + (lane & 3) * 2;   // col in block tile
        const int n = n0 + nl;
        float2 bv = *(const float2*)(bias + v * NO + n);
        float2 sum2 = make_float2(0.f, 0.f), sq2 = make_float2(0.f, 0.f);
#pragma unroll
        for (int mt = 0; mt < 4; mt++) {
            int mlo = m0 + mw + mt * 16 + (lane >> 2);
            float2 o0, o1;
            o0.x = acc[mt][nt][0] + bv.x;
            o0.y = acc[mt][nt][1] + bv.y;
            o1.x = acc[mt][nt][2] + bv.x;
            o1.y = acc[mt][nt][3] + bv.y;
            *(float2*)(g_h + (size_t)mlo * (NV * NO) + v * NO + n) = o0;
            *(float2*)(g_h + (size_t)(mlo + 8) * (NV * NO) + v * NO + n) = o1;
            sum2.x += o0.x + o1.x;
            sum2.y += o0.y + o1.y;
            sq2.x += fmaf(o0.x, o0.x, o1.x * o1.x);
            sq2.y += fmaf(o0.y, o0.y, o1.y * o1.y);
        }
#pragma unroll
        for (int msk = 4; msk <= 16; msk <<= 1) {
            sum2.x += __shfl_xor_sync(0xffffffffu, sum2.x, msk);
            sum2.y += __shfl_xor_sync(0xffffffffu, sum2.y, msk);
            sq2.x  += __shfl_xor_sync(0xffffffffu, sq2.x, msk);
            sq2.y  += __shfl_xor_sync(0xffffffffu, sq2.y, msk);
        }
        if (lane < 4) {
            atomicAdd(&g_sum[v * NO + n],     sum2.x);
            atomicAdd(&g_sum[v * NO + n + 1], sum2.y);
            atomicAdd(&g_sqs[v * NO + n],     sq2.x);
            atomicAdd(&g_sqs[v * NO + n + 1], sq2.y);
        }
    }
}

// ---------------------------------------------------------------------------
// Kernel C: finalize BN fold
// ---------------------------------------------------------------------------
__global__ __launch_bounds__(256) void stats_fin(const float* __restrict__ gamma,
                                                 const float* __restrict__ beta) {
    const int col = blockIdx.x * 256 + threadIdx.x;
    float mean = g_sum[col] * (1.f / NB);
    float var  = g_sqs[col] * (1.f / NB) - mean * mean;
    float s    = gamma[col] * rsqrtf(var + EPS);
    g_s[col] = s;
    g_t[col] = fmaf(-mean, s, beta[col]);
}

// ---------------------------------------------------------------------------
// Kernel D: tensorized mix
// ---------------------------------------------------------------------------
static constexpr int OPAD = 264;
static constexpr int HS_HI = 0;
static constexpr int HS_LO = 33792;
static constexpr int ADJ_HI = 67584;
static constexpr int ADJ_LO = 76800;
static constexpr int MIX_DSMEM = 86016 + 1024;

__global__ __launch_bounds__(256, 2) void mix_tc(float* __restrict__ out) {
    extern __shared__ char dynraw[];
    uint32_t rawa = smem_u32(dynraw);
    char* smb = dynraw + (((rawa + 1023) & ~1023u) - rawa);
    const uint32_t sbase = smem_u32(smb);

    const int b = blockIdx.x;
    const int t = threadIdx.x;
    const int lane = t & 31;
    const int w = t >> 5;

    const float4* h4 = (const float4*)(g_h + (size_t)b * NV * NO);
    const float4* s4 = (const float4*)g_s;
    const float4* t4 = (const float4*)g_t;
#pragma unroll
    for (int r = 0; r < 16; r++) {
        int idx = t + r * 256;
        int v = idx >> 6, oq = idx & 63;
        float4 h = h4[idx], sv = s4[idx], tv = t4[idx];
        float x0 = fmaf(h.x, sv.x, tv.x);
        float x1 = fmaf(h.y, sv.y, tv.y);
        float x2 = fmaf(h.z, sv.z, tv.z);
        float x3 = fmaf(h.w, sv.w, tv.w);
        __nv_bfloat16 h0 = __float2bfloat16(x0);
        __nv_bfloat16 h1 = __float2bfloat16(x1);
        __nv_bfloat16 h2 = __float2bfloat16(x2);
        __nv_bfloat16 h3 = __float2bfloat16(x3);
        __nv_bfloat16 l0 = __float2bfloat16(x0 - __bfloat162float(h0));
        __nv_bfloat16 l1 = __float2bfloat16(x1 - __bfloat162float(h1));
        __nv_bfloat16 l2 = __float2bfloat16(x2 - __bfloat162float(h2));
        __nv_bfloat16 l3 = __float2bfloat16(x3 - __bfloat162float(h3));
        __nv_bfloat162 hp0 = {h0, h1}, hp1 = {h2, h3};
        __nv_bfloat162 lp0 = {l0, l1}, lp1 = {l2, l3};
        uint32_t off = (uint32_t)(v * (OPAD * 2) + oq * 8);
        *(uint2*)(smb + HS_HI + off) =
            make_uint2(*(uint32_t*)&hp0, *(uint32_t*)&hp1);
        *(uint2*)(smb + HS_LO + off) =
            make_uint2(*(uint32_t*)&lp0, *(uint32_t*)&lp1);
    }
#pragma unroll
    for (int r = 0; r < 8; r++) {
        int idx = t + r * 256;
        int u = idx >> 5, q = idx & 31;
        *(uint32_t*)(smb + ADJ_HI + u * 144 + q * 4) =
            ((const uint32_t*)g_adjhi)[idx];
        *(uint32_t*)(smb + ADJ_LO + u * 144 + q * 4) =
            ((const uint32_t*)g_adjlo)[idx];
    }
    __syncthreads();

    const int mw = (w >> 1) * 16;
    const int nw = (w & 1) * 128;

    float acc[16][4];
#pragma unroll
    for (int i = 0; i < 16; i++)
#pragma unroll
        for (int q = 0; q < 4; q++) acc[i][q] = 0.f;

#pragma unroll
    for (int ks = 0; ks < 4; ks++) {
        uint32_t ah[4], al[4];
        uint32_t aaddr = sbase + ADJ_HI + (mw + (lane & 15)) * 144 +
                         (ks * 16 + (lane >> 4) * 8) * 2;
        ldsm_x4(ah, aaddr);
        ldsm_x4(al, aaddr + (ADJ_LO - ADJ_HI));

        uint32_t brow = sbase + HS_HI + (ks * 16 + (lane & 15)) * (OPAD * 2);
#pragma unroll
        for (int nt = 0; nt < 16; nt++) {
            int n0 = nw + nt * 8;
            uint32_t bh[2], bl[2];
            ldsm_x2t(bh, brow + n0 * 2);
            ldsm_x2t(bl, brow + n0 * 2 + (HS_LO - HS_HI));
            mma_bf16(acc[nt], ah, bh);
            mma_bf16(acc[nt], ah, bl);
            mma_bf16(acc[nt], al, bh);
        }
    }

    float* ob = out + (size_t)b * NV * NO;
    const int u0 = mw + (lane >> 2);
#pragma unroll
    for (int nt = 0; nt < 16; nt++) {
        int o = nw + nt * 8 + (lane & 3) * 2;
        float2 r0, r1;
        r0.x = fmaxf(acc[nt][0], 0.f);
        r0.y = fmaxf(acc[nt][1], 0.f);
        r1.x = fmaxf(acc[nt][2], 0.f);
        r1.y = fmaxf(acc[nt][3], 0.f);
        *(float2*)(ob + (size_t)u0 * NO + o) = r0;
        *(float2*)(ob + (size_t)(u0 + 8) * NO + o) = r1;
    }
}

// ---------------------------------------------------------------------------
extern "C" void kernel_launch(void* const* d_in, const int* in_sizes, int n_in,
                              void* d_out, int out_size) {
    const float* feat  = (const float*)d_in[0];
    const float* adj   = (const float*)d_in[1];
    const float* W     = (const float*)d_in[2];
    const float* bias  = (const float*)d_in[3];
    const float* gamma = (const float*)d_in[4];
    const float* beta  = (const float*)d_in[5];
    float* out = (float*)d_out;

    cudaFuncSetAttribute(gemm_mma, cudaFuncAttributeMaxDynamicSharedMemorySize,
                         GEMM_DSMEM);
    cudaFuncSetAttribute(mix_tc, cudaFuncAttributeMaxDynamicSharedMemorySize,
                         MIX_DSMEM);

    convert_W<<<dim3(NO / 64, NV), 256>>>(W);
    convert_adj<<<16, 256>>>(adj);   // also zeroes g_sum/g_sqs
    gemm_mma<<<dim3(NB / 128, NO / 128, NV), 256, GEMM_DSMEM>>>(feat, bias);
    stats_fin<<<64, 256>>>(gamma, beta);
    mix_tc<<<NB, 256, MIX_DSMEM>>>(out);
}